// round 11
// baseline (speedup 1.0000x reference)
#include <cuda_runtime.h>
#include <cuda_bf16.h>
#include <cstdint>
#include <math.h>

#define NN 512
#define UU 64
#define BB 128
#define MM 5
#define TSTEPS 12
#define EMAX 8192
#define SPT 32

// ------------------- static device scratch (no allocs allowed) -------------------
__device__ float g_A[NN * NN];
__device__ float g_P[2 * NN * NN];                   // dense S0, S1 (staging for CSR build)
__device__ float g_dr[NN];
__device__ float g_dc[NN];
__device__ float g_xs[(size_t)NN * 128 * BB];        // fp32 slot0 [n][c*B+b], pitch = C*128
__device__ float g_gates[(size_t)NN * 2 * UU * BB];  // [n][o(128)][b]
__device__ float g_h0[(size_t)NN * UU * BB];         // [n][u][b]
__device__ float g_h1[(size_t)NN * UU * BB];
__device__ float g_xin[NN * BB];                     // decoder input [n][b]

// CSR of S0 (s=0) and S1 (s=1): packed {col, val-bits}
__device__ int g_cnt[2][NN];
__device__ int g_rp[2][NN + 1];
__device__ int2 g_csr[2][EMAX];

// bf16 split operands
__device__ __nv_bfloat16 g_xsh[5ull * NN * 128 * BB];  // xs slots bf16 hi: [(m*512+n)][c*B+b]
__device__ __nv_bfloat16 g_xsl[5ull * NN * 128 * BB];
__device__ __nv_bfloat16 g_WTh[380928];                // W^T split hi, per-weight offsets
__device__ __nv_bfloat16 g_WTl[380928];

// ------------------------------- helpers -------------------------------
__device__ __forceinline__ uint32_t s2u32(const void* p) {
    uint32_t a;
    asm("{ .reg .u64 t; cvta.to.shared.u64 t, %1; cvt.u32.u64 %0, t; }" : "=r"(a) : "l"(p));
    return a;
}
__device__ __forceinline__ void cp16(uint32_t dst, const void* src) {
    asm volatile("cp.async.cg.shared.global [%0], [%1], 16;" :: "r"(dst), "l"(__cvta_generic_to_global(src)) : "memory");
}
__device__ __forceinline__ void cp16z(uint32_t dst, const void* src, int sz) {
    asm volatile("cp.async.cg.shared.global [%0], [%1], 16, %2;" :: "r"(dst), "l"(__cvta_generic_to_global(src)), "r"(sz) : "memory");
}
__device__ __forceinline__ void ldsm4(uint32_t* r, uint32_t addr) {
    asm volatile("ldmatrix.sync.aligned.m8n8.x4.shared.b16 {%0,%1,%2,%3}, [%4];"
                 : "=r"(r[0]), "=r"(r[1]), "=r"(r[2]), "=r"(r[3]) : "r"(addr));
}
__device__ __forceinline__ void ldsm4t(uint32_t* r, uint32_t addr) {
    asm volatile("ldmatrix.sync.aligned.m8n8.x4.trans.shared.b16 {%0,%1,%2,%3}, [%4];"
                 : "=r"(r[0]), "=r"(r[1]), "=r"(r[2]), "=r"(r[3]) : "r"(addr));
}
__device__ __forceinline__ void mma16816(float* c, const uint32_t* a, const uint32_t* b) {
    asm volatile("mma.sync.aligned.m16n8k16.row.col.f32.bf16.bf16.f32 "
                 "{%0,%1,%2,%3}, {%4,%5,%6,%7}, {%8,%9}, {%0,%1,%2,%3};"
                 : "+f"(c[0]), "+f"(c[1]), "+f"(c[2]), "+f"(c[3])
                 : "r"(a[0]), "r"(a[1]), "r"(a[2]), "r"(a[3]), "r"(b[0]), "r"(b[1]));
}

#define SWZ64(o) ((o) ^ (((o) >> 3) & 0x30))
#define SWZB(o)  ((o) ^ ((((o) >> 8) & 7) << 4))

// ------------------------------- utility kernels -------------------------------
__global__ void fill_k(float* p, int n) {
    int i = blockIdx.x * blockDim.x + threadIdx.x;
    if (i < n) p[i] = 0.f;
}

__global__ void scatter_k(const int* __restrict__ ei, const float* __restrict__ ea, int E) {
    int e = blockIdx.x * blockDim.x + threadIdx.x;
    if (e < E) atomicAdd(&g_A[ei[e] * NN + ei[E + e]], ea[e]);
}

__global__ void degree_k() {
    int i = blockIdx.x;
    float r = 0.f, c = 0.f;
    for (int j = threadIdx.x; j < NN; j += blockDim.x) {
        r += g_A[i * NN + j];
        c += g_A[j * NN + i];
    }
    __shared__ float sr[256], sc[256];
    sr[threadIdx.x] = r; sc[threadIdx.x] = c;
    __syncthreads();
    for (int s = 128; s > 0; s >>= 1) {
        if (threadIdx.x < s) { sr[threadIdx.x] += sr[threadIdx.x + s]; sc[threadIdx.x] += sc[threadIdx.x + s]; }
        __syncthreads();
    }
    if (threadIdx.x == 0) { g_dr[i] = sr[0]; g_dc[i] = sc[0]; }
}

// S0[i][j] = A[j][i]/dr[j];  S1[i][j] = A[i][j]/dc[j]
__global__ void supports_k() {
    int idx = blockIdx.x * blockDim.x + threadIdx.x;
    if (idx >= NN * NN) return;
    int i = idx / NN, j = idx % NN;
    float dr = g_dr[j], dc = g_dc[j];
    float invr = dr > 0.f ? 1.f / dr : 0.f;
    float invc = dc > 0.f ? 1.f / dc : 0.f;
    g_P[idx] = g_A[j * NN + i] * invr;
    g_P[NN * NN + idx] = g_A[i * NN + j] * invc;
}

// ---- CSR build ----
__global__ void csr_count_k() {
    int i = blockIdx.x * blockDim.x + threadIdx.x;
    if (i >= 2 * NN) return;
    int s = i >> 9, r = i & (NN - 1);
    const float* S = g_P + (size_t)s * NN * NN + (size_t)r * NN;
    int c = 0;
    for (int j = 0; j < NN; j++)
        if (S[j] != 0.f) c++;
    g_cnt[s][r] = c;
}

__global__ void csr_prefix_k() {
    __shared__ int sm[NN];
    int s = blockIdx.x;
    int tid = threadIdx.x;
    sm[tid] = g_cnt[s][tid];
    __syncthreads();
    for (int off = 1; off < NN; off <<= 1) {
        int v = (tid >= off) ? sm[tid - off] : 0;
        __syncthreads();
        sm[tid] += v;
        __syncthreads();
    }
    g_rp[s][tid + 1] = sm[tid];
    if (tid == 0) g_rp[s][0] = 0;
}

__global__ void csr_fill_k() {
    int i = blockIdx.x * blockDim.x + threadIdx.x;
    if (i >= 2 * NN) return;
    int s = i >> 9, r = i & (NN - 1);
    const float* S = g_P + (size_t)s * NN * NN + (size_t)r * NN;
    int p = g_rp[s][r];
    for (int j = 0; j < NN; j++) {
        float v = S[j];
        if (v != 0.f) { g_csr[s][p] = make_int2(j, __float_as_int(v)); p++; }
    }
}

// W [Kc][O] -> W^T split [O][Kcp] with zero pad
__global__ void wsplit_k(const float* __restrict__ W, __nv_bfloat16* oh, __nv_bfloat16* ol,
                         int Kc, int O, int Kcp) {
    int idx = blockIdx.x * blockDim.x + threadIdx.x;
    if (idx >= O * Kcp) return;
    int o = idx / Kcp, kp = idx % Kcp;
    float v = (kp < Kc) ? W[(size_t)kp * O + o] : 0.f;
    __nv_bfloat16 hi = __float2bfloat16(v);
    oh[idx] = hi;
    ol[idx] = __float2bfloat16(v - __bfloat162float(hi));
}

// ---------------------- concat: slot0 [n][c][b] = [xi ; h] (fp32 + bf16 split) ----------------------
__global__ void concat_k(const float* __restrict__ xA, int CA, int histMode,
                         const float* __restrict__ h, int C) {
    int idx = blockIdx.x * blockDim.x + threadIdx.x;
    int total = NN * C * BB;
    if (idx >= total) return;
    int b = idx & (BB - 1);
    int c = (idx / BB) % C;
    int n = idx / (BB * C);
    float v;
    if (c < CA) {
        v = histMode ? xA[b * NN + n] : xA[((size_t)n * CA + c) * BB + b];
    } else {
        int u = c - CA;
        v = h[((size_t)n * UU + u) * BB + b];
    }
    g_xs[idx] = v;
    __nv_bfloat16 hi = __float2bfloat16(v);
    g_xsh[idx] = hi;
    g_xsl[idx] = __float2bfloat16(v - __bfloat162float(hi));
}

// candidate concat: only rewrite the h-channels of slot0 with r*h
__global__ void concat_rh_k(const float* __restrict__ h, int CA, int pitch) {
    int idx = blockIdx.x * blockDim.x + threadIdx.x;
    if (idx >= NN * UU * BB) return;
    int b = idx & (BB - 1);
    int u = (idx / BB) % UU;
    int n = idx / (BB * UU);
    float r = g_gates[((size_t)n * 2 * UU + u) * BB + b];
    float v = h[((size_t)n * UU + u) * BB + b] * r;
    size_t o = (size_t)n * pitch + (CA + u) * BB + b;
    g_xs[o] = v;
    __nv_bfloat16 hi = __float2bfloat16(v);
    g_xsh[o] = hi;
    g_xsl[o] = __float2bfloat16(v - __bfloat162float(hi));
}

// =================== fused sparse diffusion: slots 1,2 (S0) / 3,4 (S1) ===================
// block: 32-col tile over all 512 nodes. x0 tile + packed CSR + row ptrs staged in smem.
// pass1: x1 = S x0 ; pass2: x2 = 2 S x1 - x0. fp32 (4-way split sums); writes bf16 hi/lo slots.
#define SPMM_SMEM (2 * NN * SPT * 4 + EMAX * 8 + (NN + 1) * 4)

__device__ __forceinline__ float spmv_row(const int2* __restrict__ scsr, int beg, int end,
                                          const float* __restrict__ X, int lane) {
    float a0 = 0.f, a1 = 0.f, a2 = 0.f, a3 = 0.f;
    int k = beg;
    for (; k + 4 <= end; k += 4) {
        int2 e0 = scsr[k], e1 = scsr[k + 1], e2 = scsr[k + 2], e3 = scsr[k + 3];
        a0 += __int_as_float(e0.y) * X[e0.x * SPT + lane];
        a1 += __int_as_float(e1.y) * X[e1.x * SPT + lane];
        a2 += __int_as_float(e2.y) * X[e2.x * SPT + lane];
        a3 += __int_as_float(e3.y) * X[e3.x * SPT + lane];
    }
    for (; k < end; k++) {
        int2 e = scsr[k];
        a0 += __int_as_float(e.y) * X[e.x * SPT + lane];
    }
    return (a0 + a1) + (a2 + a3);
}

__global__ void __launch_bounds__(1024) spmm_k(int pitch, int colbase) {
    extern __shared__ float sm[];
    float* X0 = sm;                           // [512][32]
    float* X1 = sm + NN * SPT;                // [512][32]
    int2* scsr = (int2*)(sm + 2 * NN * SPT);  // [EMAX] packed {col, val}
    int* srp = (int*)(scsr + EMAX);           // [NN+1]
    const int s = blockIdx.y;
    const int col0 = colbase + blockIdx.x * SPT;
    const int tid = threadIdx.x, lane = tid & 31, wid = tid >> 5;

    const int nnz = g_rp[s][NN];
    for (int k = tid; k < nnz; k += 1024) scsr[k] = g_csr[s][k];
    for (int k = tid; k <= NN; k += 1024) srp[k] = g_rp[s][k];
    for (int r = wid; r < NN; r += 32)
        X0[r * SPT + lane] = g_xs[(size_t)r * pitch + col0 + lane];
    __syncthreads();

    const int slot1 = s ? 3 : 1;
    const int slot2 = s ? 4 : 2;

    for (int i = wid; i < NN; i += 32) {
        float acc = spmv_row(scsr, srp[i], srp[i + 1], X0, lane);
        X1[i * SPT + lane] = acc;
        size_t o = ((size_t)(slot1 * NN + i)) * pitch + col0 + lane;
        __nv_bfloat16 hi = __float2bfloat16(acc);
        g_xsh[o] = hi;
        g_xsl[o] = __float2bfloat16(acc - __bfloat162float(hi));
    }
    __syncthreads();

    for (int i = wid; i < NN; i += 32) {
        float acc = spmv_row(scsr, srp[i], srp[i + 1], X1, lane);
        float v = 2.f * acc - X0[i * SPT + lane];
        size_t o = ((size_t)(slot2 * NN + i)) * pitch + col0 + lane;
        __nv_bfloat16 hi = __float2bfloat16(v);
        g_xsh[o] = hi;
        g_xsl[o] = __float2bfloat16(v - __bfloat162float(hi));
    }
}

// =================== tensor-core weight GEMM: out[n][o][b] = act(W^T @ xs[n] + bias) ===================
template <int O>
__device__ __forceinline__ void wcopy(uint32_t sbase, int KC, int tid, int n, int C, int Kc, int Kcp,
                                      const __nv_bfloat16* wth, const __nv_bfloat16* wtl) {
    constexpr int ABYTES = O * 64;
    const __nv_bfloat16* xh = g_xsh;
    const __nv_bfloat16* xl = g_xsl;
    const size_t npitch = (size_t)C * BB;
#pragma unroll
    for (int i = 0; i < (O * 8) / 256; i++) {
        int idx = tid + 256 * i;
        int arr = idx / (O * 4);
        int rem = idx % (O * 4);
        int o = rem >> 2, gq = rem & 3;
        const char* srcp = (const char*)(arr ? wtl : wth) +
                           ((size_t)o * Kcp + (size_t)KC * 32) * 2 + gq * 16;
        cp16(sbase + arr * ABYTES + SWZ64(o * 64 + gq * 16), srcp);
    }
#pragma unroll
    for (int i = 0; i < 4; i++) {
        int idx = tid + 256 * i;
        int arr = idx >> 9;
        int rem = idx & 511;
        int row = rem >> 4, gq = rem & 15;
        int k = KC * 32 + row;
        int cc = k / 5, mm = k - 5 * cc;
        int sz = (k < Kc) ? 16 : 0;
        if (cc > C - 1) { cc = C - 1; mm = 0; }
        const char* srcp = (const char*)((arr ? xl : xh) +
                           (size_t)(mm * 512 + n) * npitch + (size_t)cc * BB) + gq * 16;
        cp16z(sbase + 2 * ABYTES + arr * 8192 + SWZB(row * 256 + gq * 16), srcp, sz);
    }
}

// O=128: gates (sigmoid, write to out). O=64: candidate with FUSED GRU update:
//   h = u*h + (1-u)*tanh(acc+bias), written in place to hstate.   3-stage cp.async pipeline.
//   __launch_bounds__(256, 2): cap regs at 128 so 2 blocks/SM fit the register file.
template <int O, int ACT>
__global__ void __launch_bounds__(256, 2) wgemm_tc(
    const __nv_bfloat16* __restrict__ wth, const __nv_bfloat16* __restrict__ wtl,
    const float* __restrict__ bias, float* __restrict__ out,
    int C, int Kc, int Kcp, float* __restrict__ hstate)
{
    constexpr int WX = (O == 128) ? 4 : 8;
    constexpr int WN = 128 / WX;
    constexpr int NB = WN / 8;
    constexpr int ABYTES = O * 64;
    constexpr int STG = 2 * ABYTES + 16384;

    extern __shared__ char smemc[];
    uint32_t sb = s2u32(smemc);
    const int tid = threadIdx.x;
    const int wid = tid >> 5, lane = tid & 31;
    const int wm = wid / WX, wn = wid % WX;
    const int n = blockIdx.x;
    const int NCH = Kcp >> 5;

    const int lrow = (lane & 7) + ((lane >> 3) & 1) * 8;
    const int lqh = (lane >> 4) & 1;

    float acc[4][NB][4];
#pragma unroll
    for (int i = 0; i < 4; i++)
#pragma unroll
        for (int j = 0; j < NB; j++)
#pragma unroll
            for (int q = 0; q < 4; q++) acc[i][j][q] = 0.f;

    wcopy<O>(sb, 0, tid, n, C, Kc, Kcp, wth, wtl);
    asm volatile("cp.async.commit_group;" ::: "memory");
    if (NCH > 1) {
        wcopy<O>(sb + STG, 1, tid, n, C, Kc, Kcp, wth, wtl);
        asm volatile("cp.async.commit_group;" ::: "memory");
    }

    for (int kc = 0; kc < NCH; kc++) {
        const int s = kc % 3;
        if (kc + 2 < NCH) {
            wcopy<O>(sb + ((kc + 2) % 3) * STG, kc + 2, tid, n, C, Kc, Kcp, wth, wtl);
            asm volatile("cp.async.commit_group;" ::: "memory");
            asm volatile("cp.async.wait_group 2;" ::: "memory");
        } else if (kc + 1 < NCH) {
            asm volatile("cp.async.wait_group 1;" ::: "memory");
        } else {
            asm volatile("cp.async.wait_group 0;" ::: "memory");
        }
        __syncthreads();

        const uint32_t Ah = sb + s * STG;
        const uint32_t Al = Ah + ABYTES;
        const uint32_t Bh = Ah + 2 * ABYTES;
        const uint32_t Bl = Bh + 8192;

#pragma unroll
        for (int ks = 0; ks < 2; ks++) {
            const int q = ks * 2 + lqh;
            uint32_t afh[4][4], afl[4][4], bfr[NB][2];
#pragma unroll
            for (int mi = 0; mi < 4; mi++) {
                int r = wm * 64 + mi * 16 + lrow;
                uint32_t off = SWZ64(r * 64 + q * 16);
                ldsm4(afh[mi], Ah + off);
                ldsm4(afl[mi], Al + off);
            }
            const int rowk = ks * 16 + ((lane >> 3) & 1) * 8 + (lane & 7);
#pragma unroll
            for (int t = 0; t < NB / 2; t++) {
                int colb = wn * WN + t * 16 + ((lane >> 4) & 1) * 8;
                uint32_t r4[4];
                ldsm4t(r4, Bh + SWZB(rowk * 256 + colb * 2));
                bfr[2 * t][0] = r4[0]; bfr[2 * t][1] = r4[1];
                bfr[2 * t + 1][0] = r4[2]; bfr[2 * t + 1][1] = r4[3];
            }
#pragma unroll
            for (int mi = 0; mi < 4; mi++)
#pragma unroll
                for (int nj = 0; nj < NB; nj++) {
                    mma16816(acc[mi][nj], afh[mi], bfr[nj]);
                    mma16816(acc[mi][nj], afl[mi], bfr[nj]);
                }
#pragma unroll
            for (int t = 0; t < NB / 2; t++) {
                int colb = wn * WN + t * 16 + ((lane >> 4) & 1) * 8;
                uint32_t r4[4];
                ldsm4t(r4, Bl + SWZB(rowk * 256 + colb * 2));
                bfr[2 * t][0] = r4[0]; bfr[2 * t][1] = r4[1];
                bfr[2 * t + 1][0] = r4[2]; bfr[2 * t + 1][1] = r4[3];
            }
#pragma unroll
            for (int mi = 0; mi < 4; mi++)
#pragma unroll
                for (int nj = 0; nj < NB; nj++)
                    mma16816(acc[mi][nj], afh[mi], bfr[nj]);
        }
        __syncthreads();
    }

    // epilogue
    const int g = lane >> 2, tg = lane & 3;
#pragma unroll
    for (int mi = 0; mi < 4; mi++) {
#pragma unroll
        for (int nj = 0; nj < NB; nj++) {
            const float* c = acc[mi][nj];
            int o = wm * 64 + mi * 16 + g;
            int b = wn * WN + nj * 8 + tg * 2;
            float b0 = bias[o], b1 = bias[o + 8];
            float v0 = c[0] + b0, v1 = c[1] + b0;
            float v2 = c[2] + b1, v3 = c[3] + b1;
            if (ACT) {
                v0 = tanhf(v0); v1 = tanhf(v1); v2 = tanhf(v2); v3 = tanhf(v3);
                size_t gi0 = ((size_t)n * 2 * UU + UU + o) * BB + b;
                size_t gi1 = ((size_t)n * 2 * UU + UU + o + 8) * BB + b;
                float2 u0 = *(const float2*)&g_gates[gi0];
                float2 u1 = *(const float2*)&g_gates[gi1];
                size_t hi0 = ((size_t)n * UU + o) * BB + b;
                size_t hi1 = ((size_t)n * UU + o + 8) * BB + b;
                float2 h0v = *(const float2*)&hstate[hi0];
                float2 h1v = *(const float2*)&hstate[hi1];
                float2 r0, r1;
                r0.x = u0.x * h0v.x + (1.f - u0.x) * v0;
                r0.y = u0.y * h0v.y + (1.f - u0.y) * v1;
                r1.x = u1.x * h1v.x + (1.f - u1.x) * v2;
                r1.y = u1.y * h1v.y + (1.f - u1.y) * v3;
                *(float2*)&hstate[hi0] = r0;
                *(float2*)&hstate[hi1] = r1;
            } else {
                v0 = 1.f / (1.f + expf(-v0)); v1 = 1.f / (1.f + expf(-v1));
                v2 = 1.f / (1.f + expf(-v2)); v3 = 1.f / (1.f + expf(-v3));
                *(float2*)&out[((size_t)n * O + o) * BB + b] = make_float2(v0, v1);
                *(float2*)&out[((size_t)n * O + o + 8) * BB + b] = make_float2(v2, v3);
            }
        }
    }
}

// projection + decoder feed
__global__ void proj_k(const float* __restrict__ pW, const float* __restrict__ pb,
                       float* __restrict__ out, int t) {
    int n = blockIdx.x;
    int b = threadIdx.x;
    float acc = pb[0];
#pragma unroll
    for (int u = 0; u < UU; u++) acc += g_h1[((size_t)n * UU + u) * BB + b] * pW[u];
    out[(size_t)b * (TSTEPS * NN) + t * NN + n] = acc;
    g_xin[n * BB + b] = acc;
}

// ------------------------------- host orchestration -------------------------------
#define WG128_SMEM (3 * (2 * 128 * 64 + 16384))
#define WG64_SMEM  (3 * (2 * 64 * 64 + 16384))

static void run_cell(const float* xA, int CA, int histMode, float* h,
                     const __nv_bfloat16* wtgh, const __nv_bfloat16* wtgl, const float* bg,
                     const __nv_bfloat16* wtch, const __nv_bfloat16* wtcl, const float* bc,
                     float* pGates) {
    const int C = CA + UU;
    const int pitch = C * BB;
    const int Kc = C * MM;
    const int Kcp = (Kc + 31) & ~31;
    // gate path
    concat_k<<<(NN * C * BB) / 256, 256>>>(xA, CA, histMode, h, C);
    spmm_k<<<dim3(pitch / SPT, 2), 1024, SPMM_SMEM>>>(pitch, 0);
    wgemm_tc<128, 0><<<NN, 256, WG128_SMEM>>>(wtgh, wtgl, bg, pGates, C, Kc, Kcp, nullptr);
    // candidate path: only the 64 h-channels change; fused GRU update in epilogue
    concat_rh_k<<<(NN * UU * BB) / 256, 256>>>(h, CA, pitch);
    spmm_k<<<dim3((UU * BB) / SPT, 2), 1024, SPMM_SMEM>>>(pitch, CA * BB);
    wgemm_tc<64, 1><<<NN, 256, WG64_SMEM>>>(wtch, wtcl, bc, nullptr, C, Kc, Kcp, h);
}

extern "C" void kernel_launch(void* const* d_in, const int* in_sizes, int n_in,
                              void* d_out, int out_size) {
    const float* hist = (const float*)d_in[0];
    const int* ei = (const int*)d_in[1];
    const float* ea = (const float*)d_in[2];
    const float* w[16];
    for (int i = 0; i < 16; i++) w[i] = (const float*)d_in[3 + i];
    const float* pW = (const float*)d_in[19];
    const float* pb = (const float*)d_in[20];
    float* out = (float*)d_out;
    const int E = in_sizes[2];

    float *pA, *pGates, *pH0, *pH1, *pXin;
    __nv_bfloat16 *pWTh, *pWTl;
    cudaGetSymbolAddress((void**)&pA, g_A);
    cudaGetSymbolAddress((void**)&pGates, g_gates);
    cudaGetSymbolAddress((void**)&pH0, g_h0);
    cudaGetSymbolAddress((void**)&pH1, g_h1);
    cudaGetSymbolAddress((void**)&pXin, g_xin);
    cudaGetSymbolAddress((void**)&pWTh, g_WTh);
    cudaGetSymbolAddress((void**)&pWTl, g_WTl);

    cudaFuncSetAttribute(spmm_k, cudaFuncAttributeMaxDynamicSharedMemorySize, SPMM_SMEM);
    cudaFuncSetAttribute(wgemm_tc<128, 0>, cudaFuncAttributeMaxDynamicSharedMemorySize, WG128_SMEM);
    cudaFuncSetAttribute(wgemm_tc<64, 1>, cudaFuncAttributeMaxDynamicSharedMemorySize, WG64_SMEM);

    // ---- build supports + CSR ----
    fill_k<<<(NN * NN) / 256, 256>>>(pA, NN * NN);                 // launch 1
    scatter_k<<<(E + 255) / 256, 256>>>(ei, ea, E);                // launch 2
    degree_k<<<NN, 256>>>();                                       // launch 3
    // ---- instrumentation: dummy spmm at profiled slots 4-6 ----
    // First (correctness) call: g_rp is zero -> no-op. Replays: reads stale-but-
    // deterministic state; every written slot is fully overwritten by the first
    // real gate spmm before any consumer -> final output deterministic.
    spmm_k<<<dim3(512, 2), 1024, SPMM_SMEM>>>(16384, 0);           // launch 4
    spmm_k<<<dim3(512, 2), 1024, SPMM_SMEM>>>(16384, 0);           // launch 5
    spmm_k<<<dim3(512, 2), 1024, SPMM_SMEM>>>(16384, 0);           // launch 6
    supports_k<<<(NN * NN) / 256, 256>>>();
    csr_count_k<<<4, 256>>>();
    csr_prefix_k<<<2, NN>>>();
    csr_fill_k<<<4, 256>>>();

    // ---- split weights: W^T hi/lo, zero-padded ----
    const int KC0 = 325, KP0 = 352, KC1 = 640, KP1 = 640;
    size_t woff[8];
    {
        size_t o = 0;
        for (int pfx = 0; pfx < 2; pfx++) {
            woff[pfx * 4 + 0] = o; o += (size_t)128 * KP0;
            woff[pfx * 4 + 1] = o; o += (size_t)64 * KP0;
            woff[pfx * 4 + 2] = o; o += (size_t)128 * KP1;
            woff[pfx * 4 + 3] = o; o += (size_t)64 * KP1;
        }
    }
    for (int pfx = 0; pfx < 2; pfx++) {
        const float* Wg0 = w[pfx * 8 + 0]; const float* Wc0 = w[pfx * 8 + 2];
        const float* Wg1 = w[pfx * 8 + 4]; const float* Wc1 = w[pfx * 8 + 6];
        wsplit_k<<<(128 * KP0 + 255) / 256, 256>>>(Wg0, pWTh + woff[pfx * 4 + 0], pWTl + woff[pfx * 4 + 0], KC0, 128, KP0);
        wsplit_k<<<(64 * KP0 + 255) / 256, 256>>>(Wc0, pWTh + woff[pfx * 4 + 1], pWTl + woff[pfx * 4 + 1], KC0, 64, KP0);
        wsplit_k<<<(128 * KP1 + 255) / 256, 256>>>(Wg1, pWTh + woff[pfx * 4 + 2], pWTl + woff[pfx * 4 + 2], KC1, 128, KP1);
        wsplit_k<<<(64 * KP1 + 255) / 256, 256>>>(Wc1, pWTh + woff[pfx * 4 + 3], pWTl + woff[pfx * 4 + 3], KC1, 64, KP1);
    }

    // ---- init states ----
    fill_k<<<(NN * UU * BB) / 256, 256>>>(pH0, NN * UU * BB);
    fill_k<<<(NN * UU * BB) / 256, 256>>>(pH1, NN * UU * BB);
    fill_k<<<(NN * BB) / 256, 256>>>(pXin, NN * BB);

    // ---- encoder ----
    for (int t = 0; t < TSTEPS; t++) {
        run_cell(hist + (size_t)t * BB * NN, 1, 1, pH0,
                 pWTh + woff[0], pWTl + woff[0], w[1], pWTh + woff[1], pWTl + woff[1], w[3], pGates);
        run_cell(pH0, UU, 0, pH1,
                 pWTh + woff[2], pWTl + woff[2], w[5], pWTh + woff[3], pWTl + woff[3], w[7], pGates);
    }

    // ---- decoder ----
    for (int t = 0; t < TSTEPS; t++) {
        run_cell(pXin, 1, 0, pH0,
                 pWTh + woff[4], pWTl + woff[4], w[9], pWTh + woff[5], pWTl + woff[5], w[11], pGates);
        run_cell(pH0, UU, 0, pH1,
                 pWTh + woff[6], pWTl + woff[6], w[13], pWTh + woff[7], pWTl + woff[7], w[15], pGates);
        proj_k<<<NN, BB>>>(pW, pb, out, t);
    }
    (void)n_in; (void)out_size;
}

// round 16
// speedup vs baseline: 1.1352x; 1.1352x over previous
// THEORY (R16): R15 ran but FAILED correctness (rel_err 0.48): the two supports
// (blockIdx.y = s in {0,1}) both wrote x1 = S_s x0 into the SAME g_x1 scratch
// region -> race between S0 and S1 intermediates; spmm2 read garbage for one
// support. Fix: g_x1 doubled, indexed with a per-support stride.
// Underlying optimization (unrun until now): spmm is LSU-instruction-throughput
// bound (112us/launch, ~20K LDS/block, issue 45%). 64-column tiles with float2
// lanes (LDS.64 X-gathers) + CSR columns pre-scaled to byte row offsets halve
// shared-load instructions; split into spmm1 (x1 -> scratch + bf16 slot1) and
// spmm2 (x2 = 2 S x1 - x0 -> bf16 slot2) because X tile + CSR no longer fit
// twice in smem. PREDICTION: 23.7 -> ~20.3 ms (19.5-21.5); profiled spmm1_k
// ~35-45us; rel_err ~9e-6. If >=22.5 ms, merge passes with a 48-col tile next.

#include <cuda_runtime.h>
#include <cuda_bf16.h>
#include <cstdint>
#include <math.h>

#define NN 512
#define UU 64
#define BB 128
#define MM 5
#define TSTEPS 12
#define EMAX 8192
#define SPC 64   // columns per spmm block (32 float2 lanes)
#define X1STRIDE ((size_t)NN * 128 * BB)   // per-support stride in g_x1

// ------------------- static device scratch (no allocs allowed) -------------------
__device__ float g_A[NN * NN];
__device__ float g_P[2 * NN * NN];                   // dense S0, S1 (staging for CSR build)
__device__ float g_dr[NN];
__device__ float g_dc[NN];
__device__ float g_xs[(size_t)NN * 128 * BB];        // fp32 slot0 [n][c*B+b], pitch = C*128
__device__ float g_x1[2ull * NN * 128 * BB];         // fp32 x1 scratch, PER SUPPORT (s stride)
__device__ float g_gates[(size_t)NN * 2 * UU * BB];  // [n][o(128)][b]
__device__ float g_h0[(size_t)NN * UU * BB];         // [n][u][b]
__device__ float g_h1[(size_t)NN * UU * BB];
__device__ float g_xin[NN * BB];                     // decoder input [n][b]

// CSR of S0 (s=0) and S1 (s=1): packed {col*256 (byte row offset), val-bits}
__device__ int g_cnt[2][NN];
__device__ int g_rp[2][NN + 1];
__device__ int2 g_csr[2][EMAX];

// bf16 split operands
__device__ __nv_bfloat16 g_xsh[5ull * NN * 128 * BB];  // xs slots bf16 hi: [(m*512+n)][c*B+b]
__device__ __nv_bfloat16 g_xsl[5ull * NN * 128 * BB];
__device__ __nv_bfloat16 g_WTh[380928];                // W^T split hi, per-weight offsets
__device__ __nv_bfloat16 g_WTl[380928];

// ------------------------------- helpers -------------------------------
__device__ __forceinline__ uint32_t s2u32(const void* p) {
    uint32_t a;
    asm("{ .reg .u64 t; cvta.to.shared.u64 t, %1; cvt.u32.u64 %0, t; }" : "=r"(a) : "l"(p));
    return a;
}
__device__ __forceinline__ void cp16(uint32_t dst, const void* src) {
    asm volatile("cp.async.cg.shared.global [%0], [%1], 16;" :: "r"(dst), "l"(__cvta_generic_to_global(src)) : "memory");
}
__device__ __forceinline__ void cp16z(uint32_t dst, const void* src, int sz) {
    asm volatile("cp.async.cg.shared.global [%0], [%1], 16, %2;" :: "r"(dst), "l"(__cvta_generic_to_global(src)), "r"(sz) : "memory");
}
__device__ __forceinline__ void ldsm4(uint32_t* r, uint32_t addr) {
    asm volatile("ldmatrix.sync.aligned.m8n8.x4.shared.b16 {%0,%1,%2,%3}, [%4];"
                 : "=r"(r[0]), "=r"(r[1]), "=r"(r[2]), "=r"(r[3]) : "r"(addr));
}
__device__ __forceinline__ void ldsm4t(uint32_t* r, uint32_t addr) {
    asm volatile("ldmatrix.sync.aligned.m8n8.x4.trans.shared.b16 {%0,%1,%2,%3}, [%4];"
                 : "=r"(r[0]), "=r"(r[1]), "=r"(r[2]), "=r"(r[3]) : "r"(addr));
}
__device__ __forceinline__ void mma16816(float* c, const uint32_t* a, const uint32_t* b) {
    asm volatile("mma.sync.aligned.m16n8k16.row.col.f32.bf16.bf16.f32 "
                 "{%0,%1,%2,%3}, {%4,%5,%6,%7}, {%8,%9}, {%0,%1,%2,%3};"
                 : "+f"(c[0]), "+f"(c[1]), "+f"(c[2]), "+f"(c[3])
                 : "r"(a[0]), "r"(a[1]), "r"(a[2]), "r"(a[3]), "r"(b[0]), "r"(b[1]));
}
__device__ __forceinline__ uint32_t packbf2f(float a, float b) {
    __nv_bfloat162 t;
    t.x = __float2bfloat16(a); t.y = __float2bfloat16(b);
    return *(uint32_t*)&t;
}

#define SWZ64(o) ((o) ^ (((o) >> 3) & 0x30))
#define SWZB(o)  ((o) ^ ((((o) >> 8) & 7) << 4))

// ------------------------------- utility kernels -------------------------------
__global__ void fill_k(float* p, int n) {
    int i = blockIdx.x * blockDim.x + threadIdx.x;
    if (i < n) p[i] = 0.f;
}

__global__ void scatter_k(const int* __restrict__ ei, const float* __restrict__ ea, int E) {
    int e = blockIdx.x * blockDim.x + threadIdx.x;
    if (e < E) atomicAdd(&g_A[ei[e] * NN + ei[E + e]], ea[e]);
}

__global__ void degree_k() {
    int i = blockIdx.x;
    float r = 0.f, c = 0.f;
    for (int j = threadIdx.x; j < NN; j += blockDim.x) {
        r += g_A[i * NN + j];
        c += g_A[j * NN + i];
    }
    __shared__ float sr[256], sc[256];
    sr[threadIdx.x] = r; sc[threadIdx.x] = c;
    __syncthreads();
    for (int s = 128; s > 0; s >>= 1) {
        if (threadIdx.x < s) { sr[threadIdx.x] += sr[threadIdx.x + s]; sc[threadIdx.x] += sc[threadIdx.x + s]; }
        __syncthreads();
    }
    if (threadIdx.x == 0) { g_dr[i] = sr[0]; g_dc[i] = sc[0]; }
}

// S0[i][j] = A[j][i]/dr[j];  S1[i][j] = A[i][j]/dc[j]
__global__ void supports_k() {
    int idx = blockIdx.x * blockDim.x + threadIdx.x;
    if (idx >= NN * NN) return;
    int i = idx / NN, j = idx % NN;
    float dr = g_dr[j], dc = g_dc[j];
    float invr = dr > 0.f ? 1.f / dr : 0.f;
    float invc = dc > 0.f ? 1.f / dc : 0.f;
    g_P[idx] = g_A[j * NN + i] * invr;
    g_P[NN * NN + idx] = g_A[i * NN + j] * invc;
}

// ---- CSR build ----
__global__ void csr_count_k() {
    int i = blockIdx.x * blockDim.x + threadIdx.x;
    if (i >= 2 * NN) return;
    int s = i >> 9, r = i & (NN - 1);
    const float* S = g_P + (size_t)s * NN * NN + (size_t)r * NN;
    int c = 0;
    for (int j = 0; j < NN; j++)
        if (S[j] != 0.f) c++;
    g_cnt[s][r] = c;
}

__global__ void csr_prefix_k() {
    __shared__ int sm[NN];
    int s = blockIdx.x;
    int tid = threadIdx.x;
    sm[tid] = g_cnt[s][tid];
    __syncthreads();
    for (int off = 1; off < NN; off <<= 1) {
        int v = (tid >= off) ? sm[tid - off] : 0;
        __syncthreads();
        sm[tid] += v;
        __syncthreads();
    }
    g_rp[s][tid + 1] = sm[tid];
    if (tid == 0) g_rp[s][0] = 0;
}

// store column as BYTE ROW OFFSET within a 64-col fp32 tile: j * 256
__global__ void csr_fill_k() {
    int i = blockIdx.x * blockDim.x + threadIdx.x;
    if (i >= 2 * NN) return;
    int s = i >> 9, r = i & (NN - 1);
    const float* S = g_P + (size_t)s * NN * NN + (size_t)r * NN;
    int p = g_rp[s][r];
    for (int j = 0; j < NN; j++) {
        float v = S[j];
        if (v != 0.f) { g_csr[s][p] = make_int2(j * 256, __float_as_int(v)); p++; }
    }
}

// W [Kc][O] -> W^T split [O][Kcp] with zero pad
__global__ void wsplit_k(const float* __restrict__ W, __nv_bfloat16* oh, __nv_bfloat16* ol,
                         int Kc, int O, int Kcp) {
    int idx = blockIdx.x * blockDim.x + threadIdx.x;
    if (idx >= O * Kcp) return;
    int o = idx / Kcp, kp = idx % Kcp;
    float v = (kp < Kc) ? W[(size_t)kp * O + o] : 0.f;
    __nv_bfloat16 hi = __float2bfloat16(v);
    oh[idx] = hi;
    ol[idx] = __float2bfloat16(v - __bfloat162float(hi));
}

// ---------------------- concat: slot0 [n][c][b] = [xi ; h] (fp32 + bf16 split) ----------------------
__global__ void concat_k(const float* __restrict__ xA, int CA, int histMode,
                         const float* __restrict__ h, int C) {
    int idx = blockIdx.x * blockDim.x + threadIdx.x;
    int total = NN * C * BB;
    if (idx >= total) return;
    int b = idx & (BB - 1);
    int c = (idx / BB) % C;
    int n = idx / (BB * C);
    float v;
    if (c < CA) {
        v = histMode ? xA[b * NN + n] : xA[((size_t)n * CA + c) * BB + b];
    } else {
        int u = c - CA;
        v = h[((size_t)n * UU + u) * BB + b];
    }
    g_xs[idx] = v;
    __nv_bfloat16 hi = __float2bfloat16(v);
    g_xsh[idx] = hi;
    g_xsl[idx] = __float2bfloat16(v - __bfloat162float(hi));
}

// candidate concat: only rewrite the h-channels of slot0 with r*h
__global__ void concat_rh_k(const float* __restrict__ h, int CA, int pitch) {
    int idx = blockIdx.x * blockDim.x + threadIdx.x;
    if (idx >= NN * UU * BB) return;
    int b = idx & (BB - 1);
    int u = (idx / BB) % UU;
    int n = idx / (BB * UU);
    float r = g_gates[((size_t)n * 2 * UU + u) * BB + b];
    float v = h[((size_t)n * UU + u) * BB + b] * r;
    size_t o = (size_t)n * pitch + (CA + u) * BB + b;
    g_xs[o] = v;
    __nv_bfloat16 hi = __float2bfloat16(v);
    g_xsh[o] = hi;
    g_xsl[o] = __float2bfloat16(v - __bfloat162float(hi));
}

// =================== sparse diffusion, two passes, 64-col float2 tiles ===================
#define SPMM_SMEM (NN * SPC * 4 + EMAX * 8 + (NN + 1) * 4)

__device__ __forceinline__ float2 spmv_row2(const int2* __restrict__ scsr, int beg, int end,
                                            const char* __restrict__ Xb) {
    float ax0 = 0.f, ay0 = 0.f, ax1 = 0.f, ay1 = 0.f;
    int k = beg;
    for (; k + 2 <= end; k += 2) {
        int2 e0 = scsr[k], e1 = scsr[k + 1];
        float2 v0 = *(const float2*)(Xb + e0.x);
        float2 v1 = *(const float2*)(Xb + e1.x);
        float w0 = __int_as_float(e0.y), w1 = __int_as_float(e1.y);
        ax0 += w0 * v0.x; ay0 += w0 * v0.y;
        ax1 += w1 * v1.x; ay1 += w1 * v1.y;
    }
    if (k < end) {
        int2 e = scsr[k];
        float2 v = *(const float2*)(Xb + e.x);
        float w = __int_as_float(e.y);
        ax0 += w * v.x; ay0 += w * v.y;
    }
    return make_float2(ax0 + ax1, ay0 + ay1);
}

// pass1: x1 = S x0 -> g_x1 (per-support region) fp32 + bf16 slot1
__global__ void __launch_bounds__(1024) spmm1_k(int pitch, int colbase) {
    extern __shared__ float sm[];
    float2* X0 = (float2*)sm;                  // [512][32] float2 (64 cols)
    int2* scsr = (int2*)(sm + NN * SPC);       // [EMAX]
    int* srp = (int*)(scsr + EMAX);            // [NN+1]
    const int s = blockIdx.y;
    const int col0 = colbase + blockIdx.x * SPC;
    const int tid = threadIdx.x, lane = tid & 31, wid = tid >> 5;

    const int nnz = g_rp[s][NN];
    for (int k = tid; k < nnz; k += 1024) scsr[k] = g_csr[s][k];
    for (int k = tid; k <= NN; k += 1024) srp[k] = g_rp[s][k];
    for (int r = wid; r < NN; r += 32)
        X0[r * 32 + lane] = *(const float2*)&g_xs[(size_t)r * pitch + col0 + lane * 2];
    __syncthreads();

    const int slot1 = s ? 3 : 1;
    const char* Xb = (const char*)X0 + lane * 8;
    const size_t x1base = (size_t)s * X1STRIDE;

    for (int i = wid; i < NN; i += 32) {
        float2 acc = spmv_row2(scsr, srp[i], srp[i + 1], Xb);
        *(float2*)&g_x1[x1base + (size_t)i * pitch + col0 + lane * 2] = acc;
        size_t o = ((size_t)(slot1 * NN + i)) * pitch + col0 + lane * 2;
        float hx = __bfloat162float(__float2bfloat16(acc.x));
        float hy = __bfloat162float(__float2bfloat16(acc.y));
        *(uint32_t*)&g_xsh[o] = packbf2f(acc.x, acc.y);
        *(uint32_t*)&g_xsl[o] = packbf2f(acc.x - hx, acc.y - hy);
    }
}

// pass2: x2 = 2 S x1 - x0 -> bf16 slot2
__global__ void __launch_bounds__(1024) spmm2_k(int pitch, int colbase) {
    extern __shared__ float sm[];
    float2* X1 = (float2*)sm;
    int2* scsr = (int2*)(sm + NN * SPC);
    int* srp = (int*)(scsr + EMAX);
    const int s = blockIdx.y;
    const int col0 = colbase + blockIdx.x * SPC;
    const int tid = threadIdx.x, lane = tid & 31, wid = tid >> 5;

    const int nnz = g_rp[s][NN];
    for (int k = tid; k < nnz; k += 1024) scsr[k] = g_csr[s][k];
    for (int k = tid; k <= NN; k += 1024) srp[k] = g_rp[s][k];
    const size_t x1base = (size_t)s * X1STRIDE;
    for (int r = wid; r < NN; r += 32)
        X1[r * 32 + lane] = *(const float2*)&g_x1[x1base + (size_t)r * pitch + col0 + lane * 2];
    __syncthreads();

    const int slot2 = s ? 4 : 2;
    const char* Xb = (const char*)X1 + lane * 8;

    for (int i = wid; i < NN; i += 32) {
        float2 acc = spmv_row2(scsr, srp[i], srp[i + 1], Xb);
        float2 x0v = *(const float2*)&g_xs[(size_t)i * pitch + col0 + lane * 2];
        float vx = 2.f * acc.x - x0v.x;
        float vy = 2.f * acc.y - x0v.y;
        size_t o = ((size_t)(slot2 * NN + i)) * pitch + col0 + lane * 2;
        float hx = __bfloat162float(__float2bfloat16(vx));
        float hy = __bfloat162float(__float2bfloat16(vy));
        *(uint32_t*)&g_xsh[o] = packbf2f(vx, vy);
        *(uint32_t*)&g_xsl[o] = packbf2f(vx - hx, vy - hy);
    }
}

// =================== tensor-core weight GEMM: out[n][o][b] = act(W^T @ xs[n] + bias) ===================
template <int O>
__device__ __forceinline__ void wcopy(uint32_t sbase, int KC, int tid, int n, int C, int Kc, int Kcp,
                                      const __nv_bfloat16* wth, const __nv_bfloat16* wtl) {
    constexpr int ABYTES = O * 64;
    const __nv_bfloat16* xh = g_xsh;
    const __nv_bfloat16* xl = g_xsl;
    const size_t npitch = (size_t)C * BB;
#pragma unroll
    for (int i = 0; i < (O * 8) / 256; i++) {
        int idx = tid + 256 * i;
        int arr = idx / (O * 4);
        int rem = idx % (O * 4);
        int o = rem >> 2, gq = rem & 3;
        const char* srcp = (const char*)(arr ? wtl : wth) +
                           ((size_t)o * Kcp + (size_t)KC * 32) * 2 + gq * 16;
        cp16(sbase + arr * ABYTES + SWZ64(o * 64 + gq * 16), srcp);
    }
#pragma unroll
    for (int i = 0; i < 4; i++) {
        int idx = tid + 256 * i;
        int arr = idx >> 9;
        int rem = idx & 511;
        int row = rem >> 4, gq = rem & 15;
        int k = KC * 32 + row;
        int cc = k / 5, mm = k - 5 * cc;
        int sz = (k < Kc) ? 16 : 0;
        if (cc > C - 1) { cc = C - 1; mm = 0; }
        const char* srcp = (const char*)((arr ? xl : xh) +
                           (size_t)(mm * 512 + n) * npitch + (size_t)cc * BB) + gq * 16;
        cp16z(sbase + 2 * ABYTES + arr * 8192 + SWZB(row * 256 + gq * 16), srcp, sz);
    }
}

// O=128: gates (sigmoid). O=64: candidate with FUSED GRU update. 3-stage cp.async pipeline.
template <int O, int ACT>
__global__ void __launch_bounds__(256, 2) wgemm_tc(
    const __nv_bfloat16* __restrict__ wth, const __nv_bfloat16* __restrict__ wtl,
    const float* __restrict__ bias, float* __restrict__ out,
    int C, int Kc, int Kcp, float* __restrict__ hstate)
{
    constexpr int WX = (O == 128) ? 4 : 8;
    constexpr int WN = 128 / WX;
    constexpr int NB = WN / 8;
    constexpr int ABYTES = O * 64;
    constexpr int STG = 2 * ABYTES + 16384;

    extern __shared__ char smemc[];
    uint32_t sb = s2u32(smemc);
    const int tid = threadIdx.x;
    const int wid = tid >> 5, lane = tid & 31;
    const int wm = wid / WX, wn = wid % WX;
    const int n = blockIdx.x;
    const int NCH = Kcp >> 5;

    const int lrow = (lane & 7) + ((lane >> 3) & 1) * 8;
    const int lqh = (lane >> 4) & 1;

    float acc[4][NB][4];
#pragma unroll
    for (int i = 0; i < 4; i++)
#pragma unroll
        for (int j = 0; j < NB; j++)
#pragma unroll
            for (int q = 0; q < 4; q++) acc[i][j][q] = 0.f;

    wcopy<O>(sb, 0, tid, n, C, Kc, Kcp, wth, wtl);
    asm volatile("cp.async.commit_group;" ::: "memory");
    if (NCH > 1) {
        wcopy<O>(sb + STG, 1, tid, n, C, Kc, Kcp, wth, wtl);
        asm volatile("cp.async.commit_group;" ::: "memory");
    }

    for (int kc = 0; kc < NCH; kc++) {
        const int s = kc % 3;
        if (kc + 2 < NCH) {
            wcopy<O>(sb + ((kc + 2) % 3) * STG, kc + 2, tid, n, C, Kc, Kcp, wth, wtl);
            asm volatile("cp.async.commit_group;" ::: "memory");
            asm volatile("cp.async.wait_group 2;" ::: "memory");
        } else if (kc + 1 < NCH) {
            asm volatile("cp.async.wait_group 1;" ::: "memory");
        } else {
            asm volatile("cp.async.wait_group 0;" ::: "memory");
        }
        __syncthreads();

        const uint32_t Ah = sb + s * STG;
        const uint32_t Al = Ah + ABYTES;
        const uint32_t Bh = Ah + 2 * ABYTES;
        const uint32_t Bl = Bh + 8192;

#pragma unroll
        for (int ks = 0; ks < 2; ks++) {
            const int q = ks * 2 + lqh;
            uint32_t afh[4][4], afl[4][4], bfr[NB][2];
#pragma unroll
            for (int mi = 0; mi < 4; mi++) {
                int r = wm * 64 + mi * 16 + lrow;
                uint32_t off = SWZ64(r * 64 + q * 16);
                ldsm4(afh[mi], Ah + off);
                ldsm4(afl[mi], Al + off);
            }
            const int rowk = ks * 16 + ((lane >> 3) & 1) * 8 + (lane & 7);
#pragma unroll
            for (int t = 0; t < NB / 2; t++) {
                int colb = wn * WN + t * 16 + ((lane >> 4) & 1) * 8;
                uint32_t r4[4];
                ldsm4t(r4, Bh + SWZB(rowk * 256 + colb * 2));
                bfr[2 * t][0] = r4[0]; bfr[2 * t][1] = r4[1];
                bfr[2 * t + 1][0] = r4[2]; bfr[2 * t + 1][1] = r4[3];
            }
#pragma unroll
            for (int mi = 0; mi < 4; mi++)
#pragma unroll
                for (int nj = 0; nj < NB; nj++) {
                    mma16816(acc[mi][nj], afh[mi], bfr[nj]);
                    mma16816(acc[mi][nj], afl[mi], bfr[nj]);
                }
#pragma unroll
            for (int t = 0; t < NB / 2; t++) {
                int colb = wn * WN + t * 16 + ((lane >> 4) & 1) * 8;
                uint32_t r4[4];
                ldsm4t(r4, Bl + SWZB(rowk * 256 + colb * 2));
                bfr[2 * t][0] = r4[0]; bfr[2 * t][1] = r4[1];
                bfr[2 * t + 1][0] = r4[2]; bfr[2 * t + 1][1] = r4[3];
            }
#pragma unroll
            for (int mi = 0; mi < 4; mi++)
#pragma unroll
                for (int nj = 0; nj < NB; nj++)
                    mma16816(acc[mi][nj], afh[mi], bfr[nj]);
        }
        __syncthreads();
    }

    const int g = lane >> 2, tg = lane & 3;
#pragma unroll
    for (int mi = 0; mi < 4; mi++) {
#pragma unroll
        for (int nj = 0; nj < NB; nj++) {
            const float* c = acc[mi][nj];
            int o = wm * 64 + mi * 16 + g;
            int b = wn * WN + nj * 8 + tg * 2;
            float b0 = bias[o], b1 = bias[o + 8];
            float v0 = c[0] + b0, v1 = c[1] + b0;
            float v2 = c[2] + b1, v3 = c[3] + b1;
            if (ACT) {
                v0 = tanhf(v0); v1 = tanhf(v1); v2 = tanhf(v2); v3 = tanhf(v3);
                size_t gi0 = ((size_t)n * 2 * UU + UU + o) * BB + b;
                size_t gi1 = ((size_t)n * 2 * UU + UU + o + 8) * BB + b;
                float2 u0 = *(const float2*)&g_gates[gi0];
                float2 u1 = *(const float2*)&g_gates[gi1];
                size_t hi0 = ((size_t)n * UU + o) * BB + b;
                size_t hi1 = ((size_t)n * UU + o + 8) * BB + b;
                float2 h0v = *(const float2*)&hstate[hi0];
                float2 h1v = *(const float2*)&hstate[hi1];
                float2 r0, r1;
                r0.x = u0.x * h0v.x + (1.f - u0.x) * v0;
                r0.y = u0.y * h0v.y + (1.f - u0.y) * v1;
                r1.x = u1.x * h1v.x + (1.f - u1.x) * v2;
                r1.y = u1.y * h1v.y + (1.f - u1.y) * v3;
                *(float2*)&hstate[hi0] = r0;
                *(float2*)&hstate[hi1] = r1;
            } else {
                v0 = 1.f / (1.f + expf(-v0)); v1 = 1.f / (1.f + expf(-v1));
                v2 = 1.f / (1.f + expf(-v2)); v3 = 1.f / (1.f + expf(-v3));
                *(float2*)&out[((size_t)n * O + o) * BB + b] = make_float2(v0, v1);
                *(float2*)&out[((size_t)n * O + o + 8) * BB + b] = make_float2(v2, v3);
            }
        }
    }
}

// projection + decoder feed
__global__ void proj_k(const float* __restrict__ pW, const float* __restrict__ pb,
                       float* __restrict__ out, int t) {
    int n = blockIdx.x;
    int b = threadIdx.x;
    float acc = pb[0];
#pragma unroll
    for (int u = 0; u < UU; u++) acc += g_h1[((size_t)n * UU + u) * BB + b] * pW[u];
    out[(size_t)b * (TSTEPS * NN) + t * NN + n] = acc;
    g_xin[n * BB + b] = acc;
}

// ------------------------------- host orchestration -------------------------------
#define WG128_SMEM (3 * (2 * 128 * 64 + 16384))
#define WG64_SMEM  (3 * (2 * 64 * 64 + 16384))

static void run_cell(const float* xA, int CA, int histMode, float* h,
                     const __nv_bfloat16* wtgh, const __nv_bfloat16* wtgl, const float* bg,
                     const __nv_bfloat16* wtch, const __nv_bfloat16* wtcl, const float* bc,
                     float* pGates) {
    const int C = CA + UU;
    const int pitch = C * BB;
    const int Kc = C * MM;
    const int Kcp = (Kc + 31) & ~31;
    // gate path
    concat_k<<<(NN * C * BB) / 256, 256>>>(xA, CA, histMode, h, C);
    spmm1_k<<<dim3(pitch / SPC, 2), 1024, SPMM_SMEM>>>(pitch, 0);
    spmm2_k<<<dim3(pitch / SPC, 2), 1024, SPMM_SMEM>>>(pitch, 0);
    wgemm_tc<128, 0><<<NN, 256, WG128_SMEM>>>(wtgh, wtgl, bg, pGates, C, Kc, Kcp, nullptr);
    // candidate path: only the 64 h-channels change; fused GRU update in epilogue
    concat_rh_k<<<(NN * UU * BB) / 256, 256>>>(h, CA, pitch);
    spmm1_k<<<dim3((UU * BB) / SPC, 2), 1024, SPMM_SMEM>>>(pitch, CA * BB);
    spmm2_k<<<dim3((UU * BB) / SPC, 2), 1024, SPMM_SMEM>>>(pitch, CA * BB);
    wgemm_tc<64, 1><<<NN, 256, WG64_SMEM>>>(wtch, wtcl, bc, nullptr, C, Kc, Kcp, h);
}

extern "C" void kernel_launch(void* const* d_in, const int* in_sizes, int n_in,
                              void* d_out, int out_size) {
    const float* hist = (const float*)d_in[0];
    const int* ei = (const int*)d_in[1];
    const float* ea = (const float*)d_in[2];
    const float* w[16];
    for (int i = 0; i < 16; i++) w[i] = (const float*)d_in[3 + i];
    const float* pW = (const float*)d_in[19];
    const float* pb = (const float*)d_in[20];
    float* out = (float*)d_out;
    const int E = in_sizes[2];

    float *pA, *pGates, *pH0, *pH1, *pXin;
    __nv_bfloat16 *pWTh, *pWTl;
    cudaGetSymbolAddress((void**)&pA, g_A);
    cudaGetSymbolAddress((void**)&pGates, g_gates);
    cudaGetSymbolAddress((void**)&pH0, g_h0);
    cudaGetSymbolAddress((void**)&pH1, g_h1);
    cudaGetSymbolAddress((void**)&pXin, g_xin);
    cudaGetSymbolAddress((void**)&pWTh, g_WTh);
    cudaGetSymbolAddress((void**)&pWTl, g_WTl);

    cudaFuncSetAttribute(spmm1_k, cudaFuncAttributeMaxDynamicSharedMemorySize, SPMM_SMEM);
    cudaFuncSetAttribute(spmm2_k, cudaFuncAttributeMaxDynamicSharedMemorySize, SPMM_SMEM);
    cudaFuncSetAttribute(wgemm_tc<128, 0>, cudaFuncAttributeMaxDynamicSharedMemorySize, WG128_SMEM);
    cudaFuncSetAttribute(wgemm_tc<64, 1>, cudaFuncAttributeMaxDynamicSharedMemorySize, WG64_SMEM);

    // ---- build supports + CSR ----
    fill_k<<<(NN * NN) / 256, 256>>>(pA, NN * NN);                 // launch 1
    scatter_k<<<(E + 255) / 256, 256>>>(ei, ea, E);                // launch 2
    degree_k<<<NN, 256>>>();                                       // launch 3
    // ---- instrumentation: dummy spmm1 at profiled slots 4-6 ----
    // First (correctness) call: g_rp is zero -> rows compute zero. Replays read
    // stale-but-deterministic state; all written slots/scratch are fully overwritten
    // by the first real gate spmm pass pair before any consumer.
    spmm1_k<<<dim3(256, 2), 1024, SPMM_SMEM>>>(16384, 0);          // launch 4
    spmm1_k<<<dim3(256, 2), 1024, SPMM_SMEM>>>(16384, 0);          // launch 5
    spmm1_k<<<dim3(256, 2), 1024, SPMM_SMEM>>>(16384, 0);          // launch 6
    supports_k<<<(NN * NN) / 256, 256>>>();
    csr_count_k<<<4, 256>>>();
    csr_prefix_k<<<2, NN>>>();
    csr_fill_k<<<4, 256>>>();

    // ---- split weights: W^T hi/lo, zero-padded ----
    const int KC0 = 325, KP0 = 352, KC1 = 640, KP1 = 640;
    size_t woff[8];
    {
        size_t o = 0;
        for (int pfx = 0; pfx < 2; pfx++) {
            woff[pfx * 4 + 0] = o; o += (size_t)128 * KP0;
            woff[pfx * 4 + 1] = o; o += (size_t)64 * KP0;
            woff[pfx * 4 + 2] = o; o += (size_t)128 * KP1;
            woff[pfx * 4 + 3] = o; o += (size_t)64 * KP1;
        }
    }
    for (int pfx = 0; pfx < 2; pfx++) {
        const float* Wg0 = w[pfx * 8 + 0]; const float* Wc0 = w[pfx * 8 + 2];
        const float* Wg1 = w[pfx * 8 + 4]; const float* Wc1 = w[pfx * 8 + 6];
        wsplit_k<<<(128 * KP0 + 255) / 256, 256>>>(Wg0, pWTh + woff[pfx * 4 + 0], pWTl + woff[pfx * 4 + 0], KC0, 128, KP0);
        wsplit_k<<<(64 * KP0 + 255) / 256, 256>>>(Wc0, pWTh + woff[pfx * 4 + 1], pWTl + woff[pfx * 4 + 1], KC0, 64, KP0);
        wsplit_k<<<(128 * KP1 + 255) / 256, 256>>>(Wg1, pWTh + woff[pfx * 4 + 2], pWTl + woff[pfx * 4 + 2], KC1, 128, KP1);
        wsplit_k<<<(64 * KP1 + 255) / 256, 256>>>(Wc1, pWTh + woff[pfx * 4 + 3], pWTl + woff[pfx * 4 + 3], KC1, 64, KP1);
    }

    // ---- init states ----
    fill_k<<<(NN * UU * BB) / 256, 256>>>(pH0, NN * UU * BB);
    fill_k<<<(NN * UU * BB) / 256, 256>>>(pH1, NN * UU * BB);
    fill_k<<<(NN * BB) / 256, 256>>>(pXin, NN * BB);

    // ---- encoder ----
    for (int t = 0; t < TSTEPS; t++) {
        run_cell(hist + (size_t)t * BB * NN, 1, 1, pH0,
                 pWTh + woff[0], pWTl + woff[0], w[1], pWTh + woff[1], pWTl + woff[1], w[3], pGates);
        run_cell(pH0, UU, 0, pH1,
                 pWTh + woff[2], pWTl + woff[2], w[5], pWTh + woff[3], pWTl + woff[3], w[7], pGates);
    }

    // ---- decoder ----
    for (int t = 0; t < TSTEPS; t++) {
        run_cell(pXin, 1, 0, pH0,
                 pWTh + woff[4], pWTl + woff[4], w[9], pWTh + woff[5], pWTl + woff[5], w[11], pGates);
        run_cell(pH0, UU, 0, pH1,
                 pWTh + woff[6], pWTl + woff[6], w[13], pWTh + woff[7], pWTl + woff[7], w[15], pGates);
        proj_k<<<NN, BB>>>(pW, pb, out, t);
    }
    (void)n_in; (void)out_size;
}

// round 17
// speedup vs baseline: 1.1920x; 1.0500x over previous
// R17: post-mortem R16 WIN (23.7 -> 21.5 ms), spmm1_k 112 -> 57.6us as predicted
// (LSU-instruction-bound theory confirmed). This round: remove the 3 dummy
// profiling launches (~0.35ms) and vectorize concat_k / concat_rh_k to process
// two elements per thread with float2 loads + uint32 packed bf16 stores
// (halves their LSU instruction count; they touch 13 MB/cell).
// PREDICTION: 21.5 -> ~20.6 ms (20.2-21.0); rel_err unchanged ~9.1e-6.

#include <cuda_runtime.h>
#include <cuda_bf16.h>
#include <cstdint>
#include <math.h>

#define NN 512
#define UU 64
#define BB 128
#define MM 5
#define TSTEPS 12
#define EMAX 8192
#define SPC 64   // columns per spmm block (32 float2 lanes)
#define X1STRIDE ((size_t)NN * 128 * BB)   // per-support stride in g_x1

// ------------------- static device scratch (no allocs allowed) -------------------
__device__ float g_A[NN * NN];
__device__ float g_P[2 * NN * NN];                   // dense S0, S1 (staging for CSR build)
__device__ float g_dr[NN];
__device__ float g_dc[NN];
__device__ float g_xs[(size_t)NN * 128 * BB];        // fp32 slot0 [n][c*B+b], pitch = C*128
__device__ float g_x1[2ull * NN * 128 * BB];         // fp32 x1 scratch, per support
__device__ float g_gates[(size_t)NN * 2 * UU * BB];  // [n][o(128)][b]
__device__ float g_h0[(size_t)NN * UU * BB];         // [n][u][b]
__device__ float g_h1[(size_t)NN * UU * BB];
__device__ float g_xin[NN * BB];                     // decoder input [n][b]

// CSR of S0 (s=0) and S1 (s=1): packed {col*256 (byte row offset), val-bits}
__device__ int g_cnt[2][NN];
__device__ int g_rp[2][NN + 1];
__device__ int2 g_csr[2][EMAX];

// bf16 split operands
__device__ __nv_bfloat16 g_xsh[5ull * NN * 128 * BB];  // xs slots bf16 hi: [(m*512+n)][c*B+b]
__device__ __nv_bfloat16 g_xsl[5ull * NN * 128 * BB];
__device__ __nv_bfloat16 g_WTh[380928];                // W^T split hi, per-weight offsets
__device__ __nv_bfloat16 g_WTl[380928];

// ------------------------------- helpers -------------------------------
__device__ __forceinline__ uint32_t s2u32(const void* p) {
    uint32_t a;
    asm("{ .reg .u64 t; cvta.to.shared.u64 t, %1; cvt.u32.u64 %0, t; }" : "=r"(a) : "l"(p));
    return a;
}
__device__ __forceinline__ void cp16(uint32_t dst, const void* src) {
    asm volatile("cp.async.cg.shared.global [%0], [%1], 16;" :: "r"(dst), "l"(__cvta_generic_to_global(src)) : "memory");
}
__device__ __forceinline__ void cp16z(uint32_t dst, const void* src, int sz) {
    asm volatile("cp.async.cg.shared.global [%0], [%1], 16, %2;" :: "r"(dst), "l"(__cvta_generic_to_global(src)), "r"(sz) : "memory");
}
__device__ __forceinline__ void ldsm4(uint32_t* r, uint32_t addr) {
    asm volatile("ldmatrix.sync.aligned.m8n8.x4.shared.b16 {%0,%1,%2,%3}, [%4];"
                 : "=r"(r[0]), "=r"(r[1]), "=r"(r[2]), "=r"(r[3]) : "r"(addr));
}
__device__ __forceinline__ void ldsm4t(uint32_t* r, uint32_t addr) {
    asm volatile("ldmatrix.sync.aligned.m8n8.x4.trans.shared.b16 {%0,%1,%2,%3}, [%4];"
                 : "=r"(r[0]), "=r"(r[1]), "=r"(r[2]), "=r"(r[3]) : "r"(addr));
}
__device__ __forceinline__ void mma16816(float* c, const uint32_t* a, const uint32_t* b) {
    asm volatile("mma.sync.aligned.m16n8k16.row.col.f32.bf16.bf16.f32 "
                 "{%0,%1,%2,%3}, {%4,%5,%6,%7}, {%8,%9}, {%0,%1,%2,%3};"
                 : "+f"(c[0]), "+f"(c[1]), "+f"(c[2]), "+f"(c[3])
                 : "r"(a[0]), "r"(a[1]), "r"(a[2]), "r"(a[3]), "r"(b[0]), "r"(b[1]));
}
__device__ __forceinline__ uint32_t packbf2f(float a, float b) {
    __nv_bfloat162 t;
    t.x = __float2bfloat16(a); t.y = __float2bfloat16(b);
    return *(uint32_t*)&t;
}

#define SWZ64(o) ((o) ^ (((o) >> 3) & 0x30))
#define SWZB(o)  ((o) ^ ((((o) >> 8) & 7) << 4))

// ------------------------------- utility kernels -------------------------------
__global__ void fill_k(float* p, int n) {
    int i = blockIdx.x * blockDim.x + threadIdx.x;
    if (i < n) p[i] = 0.f;
}

__global__ void scatter_k(const int* __restrict__ ei, const float* __restrict__ ea, int E) {
    int e = blockIdx.x * blockDim.x + threadIdx.x;
    if (e < E) atomicAdd(&g_A[ei[e] * NN + ei[E + e]], ea[e]);
}

__global__ void degree_k() {
    int i = blockIdx.x;
    float r = 0.f, c = 0.f;
    for (int j = threadIdx.x; j < NN; j += blockDim.x) {
        r += g_A[i * NN + j];
        c += g_A[j * NN + i];
    }
    __shared__ float sr[256], sc[256];
    sr[threadIdx.x] = r; sc[threadIdx.x] = c;
    __syncthreads();
    for (int s = 128; s > 0; s >>= 1) {
        if (threadIdx.x < s) { sr[threadIdx.x] += sr[threadIdx.x + s]; sc[threadIdx.x] += sc[threadIdx.x + s]; }
        __syncthreads();
    }
    if (threadIdx.x == 0) { g_dr[i] = sr[0]; g_dc[i] = sc[0]; }
}

// S0[i][j] = A[j][i]/dr[j];  S1[i][j] = A[i][j]/dc[j]
__global__ void supports_k() {
    int idx = blockIdx.x * blockDim.x + threadIdx.x;
    if (idx >= NN * NN) return;
    int i = idx / NN, j = idx % NN;
    float dr = g_dr[j], dc = g_dc[j];
    float invr = dr > 0.f ? 1.f / dr : 0.f;
    float invc = dc > 0.f ? 1.f / dc : 0.f;
    g_P[idx] = g_A[j * NN + i] * invr;
    g_P[NN * NN + idx] = g_A[i * NN + j] * invc;
}

// ---- CSR build ----
__global__ void csr_count_k() {
    int i = blockIdx.x * blockDim.x + threadIdx.x;
    if (i >= 2 * NN) return;
    int s = i >> 9, r = i & (NN - 1);
    const float* S = g_P + (size_t)s * NN * NN + (size_t)r * NN;
    int c = 0;
    for (int j = 0; j < NN; j++)
        if (S[j] != 0.f) c++;
    g_cnt[s][r] = c;
}

__global__ void csr_prefix_k() {
    __shared__ int sm[NN];
    int s = blockIdx.x;
    int tid = threadIdx.x;
    sm[tid] = g_cnt[s][tid];
    __syncthreads();
    for (int off = 1; off < NN; off <<= 1) {
        int v = (tid >= off) ? sm[tid - off] : 0;
        __syncthreads();
        sm[tid] += v;
        __syncthreads();
    }
    g_rp[s][tid + 1] = sm[tid];
    if (tid == 0) g_rp[s][0] = 0;
}

// store column as BYTE ROW OFFSET within a 64-col fp32 tile: j * 256
__global__ void csr_fill_k() {
    int i = blockIdx.x * blockDim.x + threadIdx.x;
    if (i >= 2 * NN) return;
    int s = i >> 9, r = i & (NN - 1);
    const float* S = g_P + (size_t)s * NN * NN + (size_t)r * NN;
    int p = g_rp[s][r];
    for (int j = 0; j < NN; j++) {
        float v = S[j];
        if (v != 0.f) { g_csr[s][p] = make_int2(j * 256, __float_as_int(v)); p++; }
    }
}

// W [Kc][O] -> W^T split [O][Kcp] with zero pad
__global__ void wsplit_k(const float* __restrict__ W, __nv_bfloat16* oh, __nv_bfloat16* ol,
                         int Kc, int O, int Kcp) {
    int idx = blockIdx.x * blockDim.x + threadIdx.x;
    if (idx >= O * Kcp) return;
    int o = idx / Kcp, kp = idx % Kcp;
    float v = (kp < Kc) ? W[(size_t)kp * O + o] : 0.f;
    __nv_bfloat16 hi = __float2bfloat16(v);
    oh[idx] = hi;
    ol[idx] = __float2bfloat16(v - __bfloat162float(hi));
}

// ---------------------- concat: slot0 [n][c][b] = [xi ; h] (fp32 + bf16 split) ----------------------
// vectorized: each thread handles a (b, b+1) pair (b even). Sources are contiguous in b
// except histMode (stride NN) which is handled scalar per component.
__global__ void concat_k(const float* __restrict__ xA, int CA, int histMode,
                         const float* __restrict__ h, int C) {
    int idx = blockIdx.x * blockDim.x + threadIdx.x;  // over NN*C*BB/2 pairs
    int total = NN * C * (BB / 2);
    if (idx >= total) return;
    int bp = idx % (BB / 2);
    int c = (idx / (BB / 2)) % C;
    int n = idx / ((BB / 2) * C);
    int b = bp * 2;
    float2 v;
    if (c < CA) {
        if (histMode) {
            v.x = xA[(size_t)b * NN + n];
            v.y = xA[(size_t)(b + 1) * NN + n];
        } else {
            v = *(const float2*)&xA[((size_t)n * CA + c) * BB + b];
        }
    } else {
        v = *(const float2*)&h[((size_t)n * UU + (c - CA)) * BB + b];
    }
    size_t o = (size_t)n * ((size_t)C * BB) + (size_t)c * BB + b;
    *(float2*)&g_xs[o] = v;
    float hx = __bfloat162float(__float2bfloat16(v.x));
    float hy = __bfloat162float(__float2bfloat16(v.y));
    *(uint32_t*)&g_xsh[o] = packbf2f(v.x, v.y);
    *(uint32_t*)&g_xsl[o] = packbf2f(v.x - hx, v.y - hy);
}

// candidate concat: only rewrite the h-channels of slot0 with r*h (vectorized pairs)
__global__ void concat_rh_k(const float* __restrict__ h, int CA, int pitch) {
    int idx = blockIdx.x * blockDim.x + threadIdx.x;  // over NN*UU*BB/2
    if (idx >= NN * UU * (BB / 2)) return;
    int bp = idx % (BB / 2);
    int u = (idx / (BB / 2)) % UU;
    int n = idx / ((BB / 2) * UU);
    int b = bp * 2;
    float2 r = *(const float2*)&g_gates[((size_t)n * 2 * UU + u) * BB + b];
    float2 hv = *(const float2*)&h[((size_t)n * UU + u) * BB + b];
    float2 v = make_float2(hv.x * r.x, hv.y * r.y);
    size_t o = (size_t)n * pitch + (size_t)(CA + u) * BB + b;
    *(float2*)&g_xs[o] = v;
    float hx = __bfloat162float(__float2bfloat16(v.x));
    float hy = __bfloat162float(__float2bfloat16(v.y));
    *(uint32_t*)&g_xsh[o] = packbf2f(v.x, v.y);
    *(uint32_t*)&g_xsl[o] = packbf2f(v.x - hx, v.y - hy);
}

// =================== sparse diffusion, two passes, 64-col float2 tiles ===================
#define SPMM_SMEM (NN * SPC * 4 + EMAX * 8 + (NN + 1) * 4)

__device__ __forceinline__ float2 spmv_row2(const int2* __restrict__ scsr, int beg, int end,
                                            const char* __restrict__ Xb) {
    float ax0 = 0.f, ay0 = 0.f, ax1 = 0.f, ay1 = 0.f;
    int k = beg;
    for (; k + 2 <= end; k += 2) {
        int2 e0 = scsr[k], e1 = scsr[k + 1];
        float2 v0 = *(const float2*)(Xb + e0.x);
        float2 v1 = *(const float2*)(Xb + e1.x);
        float w0 = __int_as_float(e0.y), w1 = __int_as_float(e1.y);
        ax0 += w0 * v0.x; ay0 += w0 * v0.y;
        ax1 += w1 * v1.x; ay1 += w1 * v1.y;
    }
    if (k < end) {
        int2 e = scsr[k];
        float2 v = *(const float2*)(Xb + e.x);
        float w = __int_as_float(e.y);
        ax0 += w * v.x; ay0 += w * v.y;
    }
    return make_float2(ax0 + ax1, ay0 + ay1);
}

// pass1: x1 = S x0 -> g_x1 (per-support region) fp32 + bf16 slot1
__global__ void __launch_bounds__(1024) spmm1_k(int pitch, int colbase) {
    extern __shared__ float sm[];
    float2* X0 = (float2*)sm;                  // [512][32] float2 (64 cols)
    int2* scsr = (int2*)(sm + NN * SPC);       // [EMAX]
    int* srp = (int*)(scsr + EMAX);            // [NN+1]
    const int s = blockIdx.y;
    const int col0 = colbase + blockIdx.x * SPC;
    const int tid = threadIdx.x, lane = tid & 31, wid = tid >> 5;

    const int nnz = g_rp[s][NN];
    for (int k = tid; k < nnz; k += 1024) scsr[k] = g_csr[s][k];
    for (int k = tid; k <= NN; k += 1024) srp[k] = g_rp[s][k];
    for (int r = wid; r < NN; r += 32)
        X0[r * 32 + lane] = *(const float2*)&g_xs[(size_t)r * pitch + col0 + lane * 2];
    __syncthreads();

    const int slot1 = s ? 3 : 1;
    const char* Xb = (const char*)X0 + lane * 8;
    const size_t x1base = (size_t)s * X1STRIDE;

    for (int i = wid; i < NN; i += 32) {
        float2 acc = spmv_row2(scsr, srp[i], srp[i + 1], Xb);
        *(float2*)&g_x1[x1base + (size_t)i * pitch + col0 + lane * 2] = acc;
        size_t o = ((size_t)(slot1 * NN + i)) * pitch + col0 + lane * 2;
        float hx = __bfloat162float(__float2bfloat16(acc.x));
        float hy = __bfloat162float(__float2bfloat16(acc.y));
        *(uint32_t*)&g_xsh[o] = packbf2f(acc.x, acc.y);
        *(uint32_t*)&g_xsl[o] = packbf2f(acc.x - hx, acc.y - hy);
    }
}

// pass2: x2 = 2 S x1 - x0 -> bf16 slot2
__global__ void __launch_bounds__(1024) spmm2_k(int pitch, int colbase) {
    extern __shared__ float sm[];
    float2* X1 = (float2*)sm;
    int2* scsr = (int2*)(sm + NN * SPC);
    int* srp = (int*)(scsr + EMAX);
    const int s = blockIdx.y;
    const int col0 = colbase + blockIdx.x * SPC;
    const int tid = threadIdx.x, lane = tid & 31, wid = tid >> 5;

    const int nnz = g_rp[s][NN];
    for (int k = tid; k < nnz; k += 1024) scsr[k] = g_csr[s][k];
    for (int k = tid; k <= NN; k += 1024) srp[k] = g_rp[s][k];
    const size_t x1base = (size_t)s * X1STRIDE;
    for (int r = wid; r < NN; r += 32)
        X1[r * 32 + lane] = *(const float2*)&g_x1[x1base + (size_t)r * pitch + col0 + lane * 2];
    __syncthreads();

    const int slot2 = s ? 4 : 2;
    const char* Xb = (const char*)X1 + lane * 8;

    for (int i = wid; i < NN; i += 32) {
        float2 acc = spmv_row2(scsr, srp[i], srp[i + 1], Xb);
        float2 x0v = *(const float2*)&g_xs[(size_t)i * pitch + col0 + lane * 2];
        float vx = 2.f * acc.x - x0v.x;
        float vy = 2.f * acc.y - x0v.y;
        size_t o = ((size_t)(slot2 * NN + i)) * pitch + col0 + lane * 2;
        float hx = __bfloat162float(__float2bfloat16(vx));
        float hy = __bfloat162float(__float2bfloat16(vy));
        *(uint32_t*)&g_xsh[o] = packbf2f(vx, vy);
        *(uint32_t*)&g_xsl[o] = packbf2f(vx - hx, vy - hy);
    }
}

// =================== tensor-core weight GEMM: out[n][o][b] = act(W^T @ xs[n] + bias) ===================
template <int O>
__device__ __forceinline__ void wcopy(uint32_t sbase, int KC, int tid, int n, int C, int Kc, int Kcp,
                                      const __nv_bfloat16* wth, const __nv_bfloat16* wtl) {
    constexpr int ABYTES = O * 64;
    const __nv_bfloat16* xh = g_xsh;
    const __nv_bfloat16* xl = g_xsl;
    const size_t npitch = (size_t)C * BB;
#pragma unroll
    for (int i = 0; i < (O * 8) / 256; i++) {
        int idx = tid + 256 * i;
        int arr = idx / (O * 4);
        int rem = idx % (O * 4);
        int o = rem >> 2, gq = rem & 3;
        const char* srcp = (const char*)(arr ? wtl : wth) +
                           ((size_t)o * Kcp + (size_t)KC * 32) * 2 + gq * 16;
        cp16(sbase + arr * ABYTES + SWZ64(o * 64 + gq * 16), srcp);
    }
#pragma unroll
    for (int i = 0; i < 4; i++) {
        int idx = tid + 256 * i;
        int arr = idx >> 9;
        int rem = idx & 511;
        int row = rem >> 4, gq = rem & 15;
        int k = KC * 32 + row;
        int cc = k / 5, mm = k - 5 * cc;
        int sz = (k < Kc) ? 16 : 0;
        if (cc > C - 1) { cc = C - 1; mm = 0; }
        const char* srcp = (const char*)((arr ? xl : xh) +
                           (size_t)(mm * 512 + n) * npitch + (size_t)cc * BB) + gq * 16;
        cp16z(sbase + 2 * ABYTES + arr * 8192 + SWZB(row * 256 + gq * 16), srcp, sz);
    }
}

// O=128: gates (sigmoid). O=64: candidate with FUSED GRU update. 3-stage cp.async pipeline.
template <int O, int ACT>
__global__ void __launch_bounds__(256, 2) wgemm_tc(
    const __nv_bfloat16* __restrict__ wth, const __nv_bfloat16* __restrict__ wtl,
    const float* __restrict__ bias, float* __restrict__ out,
    int C, int Kc, int Kcp, float* __restrict__ hstate)
{
    constexpr int WX = (O == 128) ? 4 : 8;
    constexpr int WN = 128 / WX;
    constexpr int NB = WN / 8;
    constexpr int ABYTES = O * 64;
    constexpr int STG = 2 * ABYTES + 16384;

    extern __shared__ char smemc[];
    uint32_t sb = s2u32(smemc);
    const int tid = threadIdx.x;
    const int wid = tid >> 5, lane = tid & 31;
    const int wm = wid / WX, wn = wid % WX;
    const int n = blockIdx.x;
    const int NCH = Kcp >> 5;

    const int lrow = (lane & 7) + ((lane >> 3) & 1) * 8;
    const int lqh = (lane >> 4) & 1;

    float acc[4][NB][4];
#pragma unroll
    for (int i = 0; i < 4; i++)
#pragma unroll
        for (int j = 0; j < NB; j++)
#pragma unroll
            for (int q = 0; q < 4; q++) acc[i][j][q] = 0.f;

    wcopy<O>(sb, 0, tid, n, C, Kc, Kcp, wth, wtl);
    asm volatile("cp.async.commit_group;" ::: "memory");
    if (NCH > 1) {
        wcopy<O>(sb + STG, 1, tid, n, C, Kc, Kcp, wth, wtl);
        asm volatile("cp.async.commit_group;" ::: "memory");
    }

    for (int kc = 0; kc < NCH; kc++) {
        const int s = kc % 3;
        if (kc + 2 < NCH) {
            wcopy<O>(sb + ((kc + 2) % 3) * STG, kc + 2, tid, n, C, Kc, Kcp, wth, wtl);
            asm volatile("cp.async.commit_group;" ::: "memory");
            asm volatile("cp.async.wait_group 2;" ::: "memory");
        } else if (kc + 1 < NCH) {
            asm volatile("cp.async.wait_group 1;" ::: "memory");
        } else {
            asm volatile("cp.async.wait_group 0;" ::: "memory");
        }
        __syncthreads();

        const uint32_t Ah = sb + s * STG;
        const uint32_t Al = Ah + ABYTES;
        const uint32_t Bh = Ah + 2 * ABYTES;
        const uint32_t Bl = Bh + 8192;

#pragma unroll
        for (int ks = 0; ks < 2; ks++) {
            const int q = ks * 2 + lqh;
            uint32_t afh[4][4], afl[4][4], bfr[NB][2];
#pragma unroll
            for (int mi = 0; mi < 4; mi++) {
                int r = wm * 64 + mi * 16 + lrow;
                uint32_t off = SWZ64(r * 64 + q * 16);
                ldsm4(afh[mi], Ah + off);
                ldsm4(afl[mi], Al + off);
            }
            const int rowk = ks * 16 + ((lane >> 3) & 1) * 8 + (lane & 7);
#pragma unroll
            for (int t = 0; t < NB / 2; t++) {
                int colb = wn * WN + t * 16 + ((lane >> 4) & 1) * 8;
                uint32_t r4[4];
                ldsm4t(r4, Bh + SWZB(rowk * 256 + colb * 2));
                bfr[2 * t][0] = r4[0]; bfr[2 * t][1] = r4[1];
                bfr[2 * t + 1][0] = r4[2]; bfr[2 * t + 1][1] = r4[3];
            }
#pragma unroll
            for (int mi = 0; mi < 4; mi++)
#pragma unroll
                for (int nj = 0; nj < NB; nj++) {
                    mma16816(acc[mi][nj], afh[mi], bfr[nj]);
                    mma16816(acc[mi][nj], afl[mi], bfr[nj]);
                }
#pragma unroll
            for (int t = 0; t < NB / 2; t++) {
                int colb = wn * WN + t * 16 + ((lane >> 4) & 1) * 8;
                uint32_t r4[4];
                ldsm4t(r4, Bl + SWZB(rowk * 256 + colb * 2));
                bfr[2 * t][0] = r4[0]; bfr[2 * t][1] = r4[1];
                bfr[2 * t + 1][0] = r4[2]; bfr[2 * t + 1][1] = r4[3];
            }
#pragma unroll
            for (int mi = 0; mi < 4; mi++)
#pragma unroll
                for (int nj = 0; nj < NB; nj++)
                    mma16816(acc[mi][nj], afh[mi], bfr[nj]);
        }
        __syncthreads();
    }

    const int g = lane >> 2, tg = lane & 3;
#pragma unroll
    for (int mi = 0; mi < 4; mi++) {
#pragma unroll
        for (int nj = 0; nj < NB; nj++) {
            const float* c = acc[mi][nj];
            int o = wm * 64 + mi * 16 + g;
            int b = wn * WN + nj * 8 + tg * 2;
            float b0 = bias[o], b1 = bias[o + 8];
            float v0 = c[0] + b0, v1 = c[1] + b0;
            float v2 = c[2] + b1, v3 = c[3] + b1;
            if (ACT) {
                v0 = tanhf(v0); v1 = tanhf(v1); v2 = tanhf(v2); v3 = tanhf(v3);
                size_t gi0 = ((size_t)n * 2 * UU + UU + o) * BB + b;
                size_t gi1 = ((size_t)n * 2 * UU + UU + o + 8) * BB + b;
                float2 u0 = *(const float2*)&g_gates[gi0];
                float2 u1 = *(const float2*)&g_gates[gi1];
                size_t hi0 = ((size_t)n * UU + o) * BB + b;
                size_t hi1 = ((size_t)n * UU + o + 8) * BB + b;
                float2 h0v = *(const float2*)&hstate[hi0];
                float2 h1v = *(const float2*)&hstate[hi1];
                float2 r0, r1;
                r0.x = u0.x * h0v.x + (1.f - u0.x) * v0;
                r0.y = u0.y * h0v.y + (1.f - u0.y) * v1;
                r1.x = u1.x * h1v.x + (1.f - u1.x) * v2;
                r1.y = u1.y * h1v.y + (1.f - u1.y) * v3;
                *(float2*)&hstate[hi0] = r0;
                *(float2*)&hstate[hi1] = r1;
            } else {
                v0 = 1.f / (1.f + expf(-v0)); v1 = 1.f / (1.f + expf(-v1));
                v2 = 1.f / (1.f + expf(-v2)); v3 = 1.f / (1.f + expf(-v3));
                *(float2*)&out[((size_t)n * O + o) * BB + b] = make_float2(v0, v1);
                *(float2*)&out[((size_t)n * O + o + 8) * BB + b] = make_float2(v2, v3);
            }
        }
    }
}

// projection + decoder feed
__global__ void proj_k(const float* __restrict__ pW, const float* __restrict__ pb,
                       float* __restrict__ out, int t) {
    int n = blockIdx.x;
    int b = threadIdx.x;
    float acc = pb[0];
#pragma unroll
    for (int u = 0; u < UU; u++) acc += g_h1[((size_t)n * UU + u) * BB + b] * pW[u];
    out[(size_t)b * (TSTEPS * NN) + t * NN + n] = acc;
    g_xin[n * BB + b] = acc;
}

// ------------------------------- host orchestration -------------------------------
#define WG128_SMEM (3 * (2 * 128 * 64 + 16384))
#define WG64_SMEM  (3 * (2 * 64 * 64 + 16384))

static void run_cell(const float* xA, int CA, int histMode, float* h,
                     const __nv_bfloat16* wtgh, const __nv_bfloat16* wtgl, const float* bg,
                     const __nv_bfloat16* wtch, const __nv_bfloat16* wtcl, const float* bc,
                     float* pGates) {
    const int C = CA + UU;
    const int pitch = C * BB;
    const int Kc = C * MM;
    const int Kcp = (Kc + 31) & ~31;
    // gate path
    concat_k<<<(NN * C * (BB / 2)) / 256, 256>>>(xA, CA, histMode, h, C);
    spmm1_k<<<dim3(pitch / SPC, 2), 1024, SPMM_SMEM>>>(pitch, 0);
    spmm2_k<<<dim3(pitch / SPC, 2), 1024, SPMM_SMEM>>>(pitch, 0);
    wgemm_tc<128, 0><<<NN, 256, WG128_SMEM>>>(wtgh, wtgl, bg, pGates, C, Kc, Kcp, nullptr);
    // candidate path: only the 64 h-channels change; fused GRU update in epilogue
    concat_rh_k<<<(NN * UU * (BB / 2)) / 256, 256>>>(h, CA, pitch);
    spmm1_k<<<dim3((UU * BB) / SPC, 2), 1024, SPMM_SMEM>>>(pitch, CA * BB);
    spmm2_k<<<dim3((UU * BB) / SPC, 2), 1024, SPMM_SMEM>>>(pitch, CA * BB);
    wgemm_tc<64, 1><<<NN, 256, WG64_SMEM>>>(wtch, wtcl, bc, nullptr, C, Kc, Kcp, h);
}

extern "C" void kernel_launch(void* const* d_in, const int* in_sizes, int n_in,
                              void* d_out, int out_size) {
    const float* hist = (const float*)d_in[0];
    const int* ei = (const int*)d_in[1];
    const float* ea = (const float*)d_in[2];
    const float* w[16];
    for (int i = 0; i < 16; i++) w[i] = (const float*)d_in[3 + i];
    const float* pW = (const float*)d_in[19];
    const float* pb = (const float*)d_in[20];
    float* out = (float*)d_out;
    const int E = in_sizes[2];

    float *pA, *pGates, *pH0, *pH1, *pXin;
    __nv_bfloat16 *pWTh, *pWTl;
    cudaGetSymbolAddress((void**)&pA, g_A);
    cudaGetSymbolAddress((void**)&pGates, g_gates);
    cudaGetSymbolAddress((void**)&pH0, g_h0);
    cudaGetSymbolAddress((void**)&pH1, g_h1);
    cudaGetSymbolAddress((void**)&pXin, g_xin);
    cudaGetSymbolAddress((void**)&pWTh, g_WTh);
    cudaGetSymbolAddress((void**)&pWTl, g_WTl);

    cudaFuncSetAttribute(spmm1_k, cudaFuncAttributeMaxDynamicSharedMemorySize, SPMM_SMEM);
    cudaFuncSetAttribute(spmm2_k, cudaFuncAttributeMaxDynamicSharedMemorySize, SPMM_SMEM);
    cudaFuncSetAttribute(wgemm_tc<128, 0>, cudaFuncAttributeMaxDynamicSharedMemorySize, WG128_SMEM);
    cudaFuncSetAttribute(wgemm_tc<64, 1>, cudaFuncAttributeMaxDynamicSharedMemorySize, WG64_SMEM);

    // ---- build supports + CSR ----
    fill_k<<<(NN * NN) / 256, 256>>>(pA, NN * NN);
    scatter_k<<<(E + 255) / 256, 256>>>(ei, ea, E);
    degree_k<<<NN, 256>>>();
    supports_k<<<(NN * NN) / 256, 256>>>();
    csr_count_k<<<4, 256>>>();
    csr_prefix_k<<<2, NN>>>();
    csr_fill_k<<<4, 256>>>();

    // ---- split weights: W^T hi/lo, zero-padded ----
    const int KC0 = 325, KP0 = 352, KC1 = 640, KP1 = 640;
    size_t woff[8];
    {
        size_t o = 0;
        for (int pfx = 0; pfx < 2; pfx++) {
            woff[pfx * 4 + 0] = o; o += (size_t)128 * KP0;
            woff[pfx * 4 + 1] = o; o += (size_t)64 * KP0;
            woff[pfx * 4 + 2] = o; o += (size_t)128 * KP1;
            woff[pfx * 4 + 3] = o; o += (size_t)64 * KP1;
        }
    }
    for (int pfx = 0; pfx < 2; pfx++) {
        const float* Wg0 = w[pfx * 8 + 0]; const float* Wc0 = w[pfx * 8 + 2];
        const float* Wg1 = w[pfx * 8 + 4]; const float* Wc1 = w[pfx * 8 + 6];
        wsplit_k<<<(128 * KP0 + 255) / 256, 256>>>(Wg0, pWTh + woff[pfx * 4 + 0], pWTl + woff[pfx * 4 + 0], KC0, 128, KP0);
        wsplit_k<<<(64 * KP0 + 255) / 256, 256>>>(Wc0, pWTh + woff[pfx * 4 + 1], pWTl + woff[pfx * 4 + 1], KC0, 64, KP0);
        wsplit_k<<<(128 * KP1 + 255) / 256, 256>>>(Wg1, pWTh + woff[pfx * 4 + 2], pWTl + woff[pfx * 4 + 2], KC1, 128, KP1);
        wsplit_k<<<(64 * KP1 + 255) / 256, 256>>>(Wc1, pWTh + woff[pfx * 4 + 3], pWTl + woff[pfx * 4 + 3], KC1, 64, KP1);
    }

    // ---- init states ----
    fill_k<<<(NN * UU * BB) / 256, 256>>>(pH0, NN * UU * BB);
    fill_k<<<(NN * UU * BB) / 256, 256>>>(pH1, NN * UU * BB);
    fill_k<<<(NN * BB) / 256, 256>>>(pXin, NN * BB);

    // ---- encoder ----
    for (int t = 0; t < TSTEPS; t++) {
        run_cell(hist + (size_t)t * BB * NN, 1, 1, pH0,
                 pWTh + woff[0], pWTl + woff[0], w[1], pWTh + woff[1], pWTl + woff[1], w[3], pGates);
        run_cell(pH0, UU, 0, pH1,
                 pWTh + woff[2], pWTl + woff[2], w[5], pWTh + woff[3], pWTl + woff[3], w[7], pGates);
    }

    // ---- decoder ----
    for (int t = 0; t < TSTEPS; t++) {
        run_cell(pXin, 1, 0, pH0,
                 pWTh + woff[4], pWTl + woff[4], w[9], pWTh + woff[5], pWTl + woff[5], w[11], pGates);
        run_cell(pH0, UU, 0, pH1,
                 pWTh + woff[6], pWTl + woff[6], w[13], pWTh + woff[7], pWTl + woff[7], w[15], pGates);
        proj_k<<<NN, BB>>>(pW, pb, out, t);
    }
    (void)n_in; (void)out_size;
}